// round 14
// baseline (speedup 1.0000x reference)
#include <cuda_runtime.h>
#include <cuda_fp16.h>
#include <cstdint>

// Problem constants
#define BSZ      2
#define SEQLEN   2048
#define DIM      4096
#define NHEADS   32
#define NKV      8
#define HD       128
#define MROWS    (BSZ*SEQLEN)          // 4096
#define KVDIM    (NKV*HD)              // 1024

// Scratch (device globals: allocation-free rule)
__device__ __half g_qh[MROWS * DIM];         // roped Q, half
__device__ __half g_kh[MROWS * KVDIM];       // roped K, half
__device__ __half g_vh[MROWS * KVDIM];       // V, half [token][d]
__device__ __half g_ctxh[MROWS * DIM];       // attention output, half
__device__ __half g_xh[MROWS * DIM];         // x in half
__device__ __half g_wqh[DIM * DIM];          // transposed weights [N,K], half
__device__ __half g_wkh[DIM * KVDIM];
__device__ __half g_wvh[DIM * KVDIM];
__device__ __half g_woh[DIM * DIM];

// ---------------------------------------------------------------------------
// helpers
// ---------------------------------------------------------------------------
__device__ __forceinline__ void mma_f16(float d[4], const uint32_t a[4],
                                        const uint32_t b[2], const float c[4]) {
    asm volatile(
        "mma.sync.aligned.m16n8k16.row.col.f32.f16.f16.f32 "
        "{%0,%1,%2,%3}, {%4,%5,%6,%7}, {%8,%9}, {%10,%11,%12,%13};\n"
        : "=f"(d[0]), "=f"(d[1]), "=f"(d[2]), "=f"(d[3])
        : "r"(a[0]), "r"(a[1]), "r"(a[2]), "r"(a[3]),
          "r"(b[0]), "r"(b[1]),
          "f"(c[0]), "f"(c[1]), "f"(c[2]), "f"(c[3]));
}

__device__ __forceinline__ void ldsm_x4(uint32_t d[4], uint32_t addr) {
    asm volatile(
        "ldmatrix.sync.aligned.m8n8.x4.shared.b16 {%0,%1,%2,%3}, [%4];"
        : "=r"(d[0]), "=r"(d[1]), "=r"(d[2]), "=r"(d[3]) : "r"(addr));
}

__device__ __forceinline__ void ldsm_x4_trans(uint32_t d[4], uint32_t addr) {
    asm volatile(
        "ldmatrix.sync.aligned.m8n8.x4.trans.shared.b16 {%0,%1,%2,%3}, [%4];"
        : "=r"(d[0]), "=r"(d[1]), "=r"(d[2]), "=r"(d[3]) : "r"(addr));
}

__device__ __forceinline__ void cp_async16(void* smem, const void* gmem) {
    uint32_t s = (uint32_t)__cvta_generic_to_shared(smem);
    asm volatile("cp.async.cg.shared.global [%0], [%1], 16;\n" :: "r"(s), "l"(gmem));
}
__device__ __forceinline__ void cp_commit() {
    asm volatile("cp.async.commit_group;\n" ::: "memory");
}
template<int N> __device__ __forceinline__ void cp_wait() {
    asm volatile("cp.async.wait_group %0;\n" :: "n"(N) : "memory");
}

// ---------------------------------------------------------------------------
// fp32 -> half elementwise (x)
// ---------------------------------------------------------------------------
__global__ void cvt_h_kernel(const float4* __restrict__ in,
                             uint2* __restrict__ out, int n4)
{
    int i = blockIdx.x * blockDim.x + threadIdx.x;
    if (i < n4) {
        float4 v = in[i];
        __half2 lo = __floats2half2_rn(v.x, v.y);
        __half2 hi = __floats2half2_rn(v.z, v.w);
        uint2 o;
        o.x = *reinterpret_cast<uint32_t*>(&lo);
        o.y = *reinterpret_cast<uint32_t*>(&hi);
        out[i] = o;
    }
}

// ---------------------------------------------------------------------------
// Merged weight transposes: z selects {wq, wk, wv, wo}; in[K,N]f32 -> out[N,K]h
// ---------------------------------------------------------------------------
__global__ void transpose_all_kernel(
    const float* __restrict__ wq, const float* __restrict__ wk,
    const float* __restrict__ wv, const float* __restrict__ wo,
    __half* __restrict__ wqh, __half* __restrict__ wkh,
    __half* __restrict__ wvh, __half* __restrict__ woh)
{
    const int z = blockIdx.z;
    const float* in; __half* out; int N;
    if (z == 0)      { in = wq; out = wqh; N = DIM; }
    else if (z == 1) { in = wk; out = wkh; N = KVDIM; }
    else if (z == 2) { in = wv; out = wvh; N = KVDIM; }
    else             { in = wo; out = woh; N = DIM; }
    int n0 = blockIdx.x * 32;
    if (n0 >= N) return;
    __shared__ float t[32][33];
    int k0 = blockIdx.y * 32;
    int tx = threadIdx.x, ty = threadIdx.y;
#pragma unroll
    for (int i = 0; i < 4; i++)
        t[ty + 8 * i][tx] = in[(size_t)(k0 + ty + 8 * i) * N + n0 + tx];
    __syncthreads();
#pragma unroll
    for (int i = 0; i < 4; i++)
        out[(size_t)(n0 + ty + 8 * i) * DIM + k0 + tx] = __float2half_rn(t[tx][ty + 8 * i]);
}

// ---------------------------------------------------------------------------
// GEMM v5 core: 128x256 CTA tile, BK=64, 256 threads (8 warps 2x4, warp 64x64),
// 4-stage cp.async, all fragments via ldmatrix, fp32 accum.
// ---------------------------------------------------------------------------
#define HSTR 72                       // halfs per smem row (144 B)
#define HSTRB 144
#define V5_A_H (128 * HSTR)           // A tile halfs
#define V5_STG_H (384 * HSTR)         // stage halfs (A 128 rows + B 256 rows)
#define V5_NSTG 4
#define GEMM_SMEM (V5_NSTG * V5_STG_H * 2)   // 221184 B -> 1 CTA/SM

struct GemmCore {
    uint32_t sm_u32;
    int tid, lane, warp, g, t4, wm, wn, lm, rr, lrow, lchk;
    uint32_t aoff, boff;
    __device__ __forceinline__ void init(const void* smem) {
        sm_u32 = (uint32_t)__cvta_generic_to_shared(smem);
        tid = threadIdx.x; lane = tid & 31; warp = tid >> 5;
        g = lane >> 2; t4 = lane & 3;
        wm = warp >> 2; wn = warp & 3;          // 2 x 4 warp grid
        lm = lane >> 3; rr = lane & 7;
        aoff = (uint32_t)((wm * 64 + (lm & 1) * 8 + rr) * HSTRB + (lm >> 1) * 16);
        boff = (uint32_t)((wn * 64 + (lm >> 1) * 8 + rr) * HSTRB + (lm & 1) * 16);
        lrow = tid >> 3; lchk = tid & 7;        // 32 rows/pass, 8 x 16B chunks
    }
};

__device__ __forceinline__ void gemm_mainloop_v5(
    GemmCore& c, __half* smh, const __half* __restrict__ A,
    const __half* __restrict__ Bt, int bm, int bn, int lda, int ldb,
    int ktiles, float acc[4][8][4])
{
#pragma unroll
    for (int mi = 0; mi < 4; mi++)
#pragma unroll
        for (int ni = 0; ni < 8; ni++)
#pragma unroll
            for (int e = 0; e < 4; e++) acc[mi][ni][e] = 0.f;

    auto issue = [&](int stg, int t) {
        if (t < ktiles) {
            __half* As = smh + stg * V5_STG_H;
            __half* Bs = As + V5_A_H;
            const int kc = t * 64 + c.lchk * 8;
#pragma unroll
            for (int p = 0; p < 4; p++) {
                int row = c.lrow + p * 32;
                cp_async16(&As[row * HSTR + c.lchk * 8],
                           &A[(size_t)(bm + row) * lda + kc]);
            }
#pragma unroll
            for (int p = 0; p < 8; p++) {
                int row = c.lrow + p * 32;
                cp_async16(&Bs[row * HSTR + c.lchk * 8],
                           &Bt[(size_t)(bn + row) * ldb + kc]);
            }
        }
        cp_commit();
    };

    issue(0, 0);
    issue(1, 1);
    issue(2, 2);

    for (int t = 0; t < ktiles; t++) {
        cp_wait<2>();
        __syncthreads();
        issue((t + 3) & 3, t + 3);

        const uint32_t aBase = c.sm_u32 + (uint32_t)((t & 3) * V5_STG_H * 2) + c.aoff;
        const uint32_t bBase = c.sm_u32 + (uint32_t)((t & 3) * V5_STG_H * 2)
                             + (uint32_t)(V5_A_H * 2) + c.boff;

#pragma unroll
        for (int ks = 0; ks < 4; ks++) {
            uint32_t a[4][4], b[4][4];
#pragma unroll
            for (int mi = 0; mi < 4; mi++)
                ldsm_x4(a[mi], aBase + mi * 16 * HSTRB + ks * 32);
#pragma unroll
            for (int p = 0; p < 4; p++)
                ldsm_x4(b[p], bBase + p * 16 * HSTRB + ks * 32);
#pragma unroll
            for (int mi = 0; mi < 4; mi++)
#pragma unroll
                for (int ni = 0; ni < 8; ni++)
                    mma_f16(acc[mi][ni], a[mi], &b[ni >> 1][(ni & 1) * 2], acc[mi][ni]);
        }
    }
}

// ---------------------------------------------------------------------------
// Merged projection GEMM (one launch: 512 wq + 128 wk + 128 wv tiles).
// Q/K epilogues fuse RoPE (fp32) and emit half; V emits plain half [token][d].
// ---------------------------------------------------------------------------
__global__ __launch_bounds__(256) void proj_gemm_kernel(
    const __half* __restrict__ xh,
    const __half* __restrict__ wqh, const __half* __restrict__ wkh,
    const __half* __restrict__ wvh,
    __half* __restrict__ qh, __half* __restrict__ kh, __half* __restrict__ vh,
    const float* __restrict__ fc, const float* __restrict__ fs)
{
    extern __shared__ __half smh[];
    GemmCore c; c.init(smh);

    const int bid = blockIdx.x;
    int mode, bx, by;
    const __half* Bt;
    if (bid < 512)      { mode = 0; by = bid >> 4; bx = bid & 15; Bt = wqh; }
    else if (bid < 640) { int t = bid - 512; mode = 1; by = t >> 2; bx = t & 3; Bt = wkh; }
    else                { int t = bid - 640; mode = 2; by = t >> 2; bx = t & 3; Bt = wvh; }

    const int bm = by * 128, bn = bx * 256;
    float acc[4][8][4];
    gemm_mainloop_v5(c, smh, xh, Bt, bm, bn, DIM, DIM, DIM / 64, acc);

    if (mode == 2) {
        // V: plain half store [token][d]
#pragma unroll
        for (int mi = 0; mi < 4; mi++)
#pragma unroll
            for (int ni = 0; ni < 8; ni++) {
                int r0 = bm + c.wm * 64 + mi * 16 + c.g;
                int cc = bn + c.wn * 64 + ni * 8 + c.t4 * 2;
                *reinterpret_cast<__half2*>(&vh[(size_t)r0 * KVDIM + cc]) =
                    __floats2half2_rn(acc[mi][ni][0], acc[mi][ni][1]);
                *reinterpret_cast<__half2*>(&vh[(size_t)(r0 + 8) * KVDIM + cc]) =
                    __floats2half2_rn(acc[mi][ni][2], acc[mi][ni][3]);
            }
    } else {
        // Q/K: fused RoPE on (even, odd) fp32 pair, emit half2
        __half* out = mode ? kh : qh;
        const int ldc = mode ? KVDIM : DIM;
#pragma unroll
        for (int mi = 0; mi < 4; mi++)
#pragma unroll
            for (int ni = 0; ni < 8; ni++) {
                int r0 = bm + c.wm * 64 + mi * 16 + c.g;
                int cc = bn + c.wn * 64 + ni * 8 + c.t4 * 2;
                int fi = (cc & (HD - 1)) >> 1;
                int s0 = r0 & (SEQLEN - 1), s1 = (r0 + 8) & (SEQLEN - 1);
                float c0 = fc[s0 * 64 + fi], n0 = fs[s0 * 64 + fi];
                float c1 = fc[s1 * 64 + fi], n1 = fs[s1 * 64 + fi];
                float e0 = acc[mi][ni][0], o0 = acc[mi][ni][1];
                float e1 = acc[mi][ni][2], o1 = acc[mi][ni][3];
                *reinterpret_cast<__half2*>(&out[(size_t)r0 * ldc + cc]) =
                    __floats2half2_rn(e0 * c0 - o0 * n0, e0 * n0 + o0 * c0);
                *reinterpret_cast<__half2*>(&out[(size_t)(r0 + 8) * ldc + cc]) =
                    __floats2half2_rn(e1 * c1 - o1 * n1, e1 * n1 + o1 * c1);
            }
    }
}

// ---------------------------------------------------------------------------
// Output-projection GEMM (half A/B, fp32 C), v5 tiles
// ---------------------------------------------------------------------------
__global__ __launch_bounds__(256) void gemm_f16_kernel(
    const __half* __restrict__ A, const __half* __restrict__ Bt,
    float* __restrict__ C, int M, int N, int K, int lda, int ldb, int ldc)
{
    extern __shared__ __half smh[];
    GemmCore c; c.init(smh);
    const int bm = blockIdx.y * 128, bn = blockIdx.x * 256;
    float acc[4][8][4];
    gemm_mainloop_v5(c, smh, A, Bt, bm, bn, lda, ldb, K / 64, acc);
#pragma unroll
    for (int mi = 0; mi < 4; mi++)
#pragma unroll
        for (int ni = 0; ni < 8; ni++) {
            int r0 = bm + c.wm * 64 + mi * 16 + c.g;
            int cc = bn + c.wn * 64 + ni * 8 + c.t4 * 2;
            *reinterpret_cast<float2*>(&C[(size_t)r0 * ldc + cc]) =
                make_float2(acc[mi][ni][0], acc[mi][ni][1]);
            *reinterpret_cast<float2*>(&C[(size_t)(r0 + 8) * ldc + cc]) =
                make_float2(acc[mi][ni][2], acc[mi][ni][3]);
        }
}

// ---------------------------------------------------------------------------
// Flash attention v5 (causal, GQA), fp16 operands, fp32 accum/softmax.
// 128 q-rows/CTA, 256 threads, Q in regs, 64-key j-tiles, LPT ordering.
// V loaded in K-layout [key][d]; PV B-fragments via ldmatrix.trans.
// ---------------------------------------------------------------------------
#define KSTRH 136                 // K/V/Q-stage smem stride in halfs (272 B)
#define VSTRH 72                  // P smem stride in halfs (144 B)
#define KT_H (64 * KSTRH)         // 8704 halfs (K or V tile)
#define PQ_H (128 * KSTRH)        // 17408 halfs (Q staging; P reuses at VSTRH)
#define ATTN_SMEM ((4 * KT_H + PQ_H) * 2)   // 104448 B

__global__ __launch_bounds__(256) void attn_kernel(
    const __half* __restrict__ Qh, const __half* __restrict__ Kh,
    const __half* __restrict__ Vh, __half* __restrict__ ctxh)
{
    extern __shared__ __half smh[];
    __half* Ksb[2] = { smh, smh + KT_H };
    __half* Vsb[2] = { smh + 2 * KT_H, smh + 3 * KT_H };
    __half* Ps     = smh + 4 * KT_H;
    const uint32_t sm_u32 = (uint32_t)__cvta_generic_to_shared(smh);
    const uint32_t ks_u[2] = { sm_u32, sm_u32 + KT_H * 2 };
    const uint32_t vs_u[2] = { sm_u32 + 2 * KT_H * 2, sm_u32 + 3 * KT_H * 2 };
    const uint32_t ps_u = sm_u32 + 4 * KT_H * 2;

    const int hb = blockIdx.x;
    const int h = hb & (NHEADS - 1), b = hb >> 5;
    const int qt = (gridDim.y - 1) - blockIdx.y;          // LPT
    const int hkv = h >> 2;
    const int tid = threadIdx.x, lane = tid & 31, warp = tid >> 5;
    const int g = lane >> 2, t4 = lane & 3;
    const int lm = lane >> 3, rr = lane & 7;

    const uint32_t qoff = (uint32_t)((warp * 16 + (lm & 1) * 8 + rr) * (KSTRH * 2) + (lm >> 1) * 16);
    const uint32_t poff = (uint32_t)((warp * 16 + (lm & 1) * 8 + rr) * (VSTRH * 2) + (lm >> 1) * 16);
    const uint32_t koff = (uint32_t)(((lm >> 1) * 8 + rr) * (KSTRH * 2) + (lm & 1) * 16);
    // V trans-frag: matrix lm = (d-half = lm>>1, k-half = lm&1)
    const uint32_t voff = (uint32_t)(((lm & 1) * 8 + rr) * (KSTRH * 2) + (lm >> 1) * 16);

    // Stage Q (128 x 128 halfs) into Ps (stride KSTRH), then pull into regs
    {
        const int r0 = tid >> 4, c8 = (tid & 15) * 8;
#pragma unroll
        for (int p = 0; p < 8; p++) {
            int r = r0 + p * 16;
            int gr = b * SEQLEN + qt * 128 + r;
            *reinterpret_cast<uint4*>(&Ps[r * KSTRH + c8]) =
                *reinterpret_cast<const uint4*>(&Qh[(size_t)gr * DIM + h * HD + c8]);
        }
    }
    __syncthreads();
    uint32_t qf[8][4];
#pragma unroll
    for (int ks = 0; ks < 8; ks++)
        ldsm_x4(qf[ks], ps_u + qoff + ks * 32);

    auto issue_kv = [&](int buf, int j) {
        __half* Ks = Ksb[buf];
        __half* Vs = Vsb[buf];
        const int kr0 = tid >> 4, kc8 = (tid & 15) * 8;
#pragma unroll
        for (int p = 0; p < 4; p++) {
            int r = kr0 + p * 16;
            int gr = b * SEQLEN + j * 64 + r;
            cp_async16(&Ks[r * KSTRH + kc8], &Kh[(size_t)gr * KVDIM + hkv * HD + kc8]);
            cp_async16(&Vs[r * KSTRH + kc8], &Vh[(size_t)gr * KVDIM + hkv * HD + kc8]);
        }
        cp_commit();
    };

    float m_s[2] = {-1e30f, -1e30f};
    float l_s[2] = {0.f, 0.f};
    float o[16][4];
#pragma unroll
    for (int di = 0; di < 16; di++)
#pragma unroll
        for (int e = 0; e < 4; e++) o[di][e] = 0.f;

    const float scale = 0.08838834764831845f;
    const int rowbase = qt * 128 + warp * 16;
    const int jmax = 2 * qt + 1;

    issue_kv(0, 0);

    for (int j = 0; j <= jmax; j++) {
        cp_wait<0>();
        __syncthreads();
        if (j + 1 <= jmax) issue_kv((j + 1) & 1, j + 1);

        const bool skip = (j * 64) > rowbase + 15;
        if (!skip) {
            const uint32_t kb = ks_u[j & 1] + koff;
            const uint32_t vb = vs_u[j & 1] + voff;

            float s[8][4];
#pragma unroll
            for (int ni = 0; ni < 8; ni++)
#pragma unroll
                for (int e = 0; e < 4; e++) s[ni][e] = 0.f;

#pragma unroll
            for (int ks = 0; ks < 8; ks++) {
                uint32_t kf[4][4];
#pragma unroll
                for (int p = 0; p < 4; p++)
                    ldsm_x4(kf[p], kb + p * 16 * (KSTRH * 2) + ks * 32);
#pragma unroll
                for (int ni = 0; ni < 8; ni++)
                    mma_f16(s[ni], qf[ks], &kf[ni >> 1][(ni & 1) * 2], s[ni]);
            }

#pragma unroll
            for (int ni = 0; ni < 8; ni++)
#pragma unroll
                for (int e = 0; e < 4; e++) s[ni][e] *= scale;
            if (j * 64 + 63 > rowbase) {
#pragma unroll
                for (int ni = 0; ni < 8; ni++)
#pragma unroll
                    for (int e = 0; e < 4; e++) {
                        int qr = rowbase + g + (e >> 1) * 8;
                        int kc = j * 64 + ni * 8 + t4 * 2 + (e & 1);
                        if (kc > qr) s[ni][e] = -1e30f;
                    }
            }

#pragma unroll
            for (int rw = 0; rw < 2; rw++) {
                float mx = -1e30f;
#pragma unroll
                for (int ni = 0; ni < 8; ni++)
                    mx = fmaxf(mx, fmaxf(s[ni][rw * 2], s[ni][rw * 2 + 1]));
                mx = fmaxf(mx, __shfl_xor_sync(0xffffffffu, mx, 1));
                mx = fmaxf(mx, __shfl_xor_sync(0xffffffffu, mx, 2));
                float nm = fmaxf(m_s[rw], mx);
                float alpha = __expf(m_s[rw] - nm);
                m_s[rw] = nm;
                float rsum = 0.f;
#pragma unroll
                for (int ni = 0; ni < 8; ni++) {
#pragma unroll
                    for (int cc = 0; cc < 2; cc++) {
                        float pv = __expf(s[ni][rw * 2 + cc] - nm);
                        s[ni][rw * 2 + cc] = pv;
                        rsum += pv;
                    }
                }
                rsum += __shfl_xor_sync(0xffffffffu, rsum, 1);
                rsum += __shfl_xor_sync(0xffffffffu, rsum, 2);
                l_s[rw] = l_s[rw] * alpha + rsum;
#pragma unroll
                for (int di = 0; di < 16; di++) {
                    o[di][rw * 2] *= alpha;
                    o[di][rw * 2 + 1] *= alpha;
                }
            }

            __syncwarp();
#pragma unroll
            for (int ni = 0; ni < 8; ni++)
#pragma unroll
                for (int rw = 0; rw < 2; rw++) {
                    int pr = warp * 16 + g + rw * 8;
                    int pc = ni * 8 + t4 * 2;
                    *reinterpret_cast<__half2*>(&Ps[pr * VSTRH + pc]) =
                        __floats2half2_rn(s[ni][rw * 2], s[ni][rw * 2 + 1]);
                }
            __syncwarp();

            // O += P @ V : V B-frags via trans-ldsm on [key][d] tile
#pragma unroll
            for (int ks = 0; ks < 4; ks++) {
                uint32_t a[4], vf[8][4];
                ldsm_x4(a, ps_u + poff + ks * 32);
#pragma unroll
                for (int p = 0; p < 8; p++)
                    ldsm_x4_trans(vf[p], vb + ks * 16 * (KSTRH * 2) + p * 32);
#pragma unroll
                for (int di = 0; di < 16; di++)
                    mma_f16(o[di], a, &vf[di >> 1][(di & 1) * 2], o[di]);
            }
        }
    }

#pragma unroll
    for (int rw = 0; rw < 2; rw++) {
        float inv = 1.0f / l_s[rw];
        int gr = b * SEQLEN + rowbase + g + rw * 8;
#pragma unroll
        for (int di = 0; di < 16; di++) {
            *reinterpret_cast<__half2*>(
                &ctxh[(size_t)gr * DIM + h * HD + di * 8 + t4 * 2]) =
                __floats2half2_rn(o[di][rw * 2] * inv, o[di][rw * 2 + 1] * inv);
        }
    }
}

// ---------------------------------------------------------------------------
// launch
// ---------------------------------------------------------------------------
extern "C" void kernel_launch(void* const* d_in, const int* in_sizes, int n_in,
                              void* d_out, int out_size)
{
    const float* x  = (const float*)d_in[0];
    const float* wq = (const float*)d_in[1];
    const float* wk = (const float*)d_in[2];
    const float* wv = (const float*)d_in[3];
    const float* wo = (const float*)d_in[4];
    const float* fc = (const float*)d_in[5];
    const float* fs = (const float*)d_in[6];
    // d_in[7] = mask (causal, applied analytically), d_in[8] = start_pos (0)
    float* out = (float*)d_out;

    __half *qh, *kh, *vh, *ctxh, *xh, *wqh, *wkh, *wvh, *woh;
    cudaGetSymbolAddress((void**)&qh,   g_qh);
    cudaGetSymbolAddress((void**)&kh,   g_kh);
    cudaGetSymbolAddress((void**)&vh,   g_vh);
    cudaGetSymbolAddress((void**)&ctxh, g_ctxh);
    cudaGetSymbolAddress((void**)&xh,   g_xh);
    cudaGetSymbolAddress((void**)&wqh,  g_wqh);
    cudaGetSymbolAddress((void**)&wkh,  g_wkh);
    cudaGetSymbolAddress((void**)&wvh,  g_wvh);
    cudaGetSymbolAddress((void**)&woh,  g_woh);

    cudaFuncSetAttribute(proj_gemm_kernel,
                         cudaFuncAttributeMaxDynamicSharedMemorySize, GEMM_SMEM);
    cudaFuncSetAttribute(gemm_f16_kernel,
                         cudaFuncAttributeMaxDynamicSharedMemorySize, GEMM_SMEM);
    cudaFuncSetAttribute(attn_kernel,
                         cudaFuncAttributeMaxDynamicSharedMemorySize, ATTN_SMEM);

    // x -> half; all 4 weight transposes in ONE launch
    int n4_big = MROWS * DIM / 4;
    cvt_h_kernel<<<(n4_big + 255) / 256, 256>>>((const float4*)x, (uint2*)xh, n4_big);
    transpose_all_kernel<<<dim3(DIM / 32, DIM / 32, 4), dim3(32, 8)>>>(
        wq, wk, wv, wo, wqh, wkh, wvh, woh);

    // ALL projections in ONE launch (512 wq + 128 wk + 128 wv tiles);
    // RoPE fused into Q/K epilogues, V emitted as half directly
    proj_gemm_kernel<<<768, 256, GEMM_SMEM>>>(xh, wqh, wkh, wvh, qh, kh, vh, fc, fs);

    // Causal flash attention (half in/out), trans-ldsm V path, LPT-ordered
    attn_kernel<<<dim3(NHEADS * BSZ, SEQLEN / 128), 256, ATTN_SMEM>>>(qh, kh, vh, ctxh);

    // Output projection (half ctx @ half wo -> fp32 out)
    gemm_f16_kernel<<<dim3(DIM / 256, MROWS / 128), 256, GEMM_SMEM>>>(
        ctxh, woh, out, MROWS, DIM, DIM, DIM, DIM, DIM);
}

// round 17
// speedup vs baseline: 1.0837x; 1.0837x over previous
#include <cuda_runtime.h>
#include <cuda_fp16.h>
#include <cstdint>

// Problem constants
#define BSZ      2
#define SEQLEN   2048
#define DIM      4096
#define NHEADS   32
#define NKV      8
#define HD       128
#define MROWS    (BSZ*SEQLEN)          // 4096
#define KVDIM    (NKV*HD)              // 1024

// Scratch (device globals: allocation-free rule)
__device__ __half g_qh[MROWS * DIM];         // roped Q, half
__device__ __half g_kh[MROWS * KVDIM];       // roped K, half
__device__ __half g_vh[MROWS * KVDIM];       // V, half [token][d]
__device__ __half g_ctxh[MROWS * DIM];       // attention output, half
__device__ __half g_xh[MROWS * DIM];         // x in half
__device__ __half g_wqh[DIM * DIM];          // transposed weights [N,K], half
__device__ __half g_wkh[DIM * KVDIM];
__device__ __half g_wvh[DIM * KVDIM];
__device__ __half g_woh[DIM * DIM];

// ---------------------------------------------------------------------------
// helpers
// ---------------------------------------------------------------------------
__device__ __forceinline__ void mma_f16(float d[4], const uint32_t a[4],
                                        const uint32_t b[2], const float c[4]) {
    asm volatile(
        "mma.sync.aligned.m16n8k16.row.col.f32.f16.f16.f32 "
        "{%0,%1,%2,%3}, {%4,%5,%6,%7}, {%8,%9}, {%10,%11,%12,%13};\n"
        : "=f"(d[0]), "=f"(d[1]), "=f"(d[2]), "=f"(d[3])
        : "r"(a[0]), "r"(a[1]), "r"(a[2]), "r"(a[3]),
          "r"(b[0]), "r"(b[1]),
          "f"(c[0]), "f"(c[1]), "f"(c[2]), "f"(c[3]));
}

__device__ __forceinline__ void ldsm_x4(uint32_t d[4], uint32_t addr) {
    asm volatile(
        "ldmatrix.sync.aligned.m8n8.x4.shared.b16 {%0,%1,%2,%3}, [%4];"
        : "=r"(d[0]), "=r"(d[1]), "=r"(d[2]), "=r"(d[3]) : "r"(addr));
}

__device__ __forceinline__ void ldsm_x4_trans(uint32_t d[4], uint32_t addr) {
    asm volatile(
        "ldmatrix.sync.aligned.m8n8.x4.trans.shared.b16 {%0,%1,%2,%3}, [%4];"
        : "=r"(d[0]), "=r"(d[1]), "=r"(d[2]), "=r"(d[3]) : "r"(addr));
}

__device__ __forceinline__ void cp_async16(void* smem, const void* gmem) {
    uint32_t s = (uint32_t)__cvta_generic_to_shared(smem);
    asm volatile("cp.async.cg.shared.global [%0], [%1], 16;\n" :: "r"(s), "l"(gmem));
}
__device__ __forceinline__ void cp_commit() {
    asm volatile("cp.async.commit_group;\n" ::: "memory");
}
template<int N> __device__ __forceinline__ void cp_wait() {
    asm volatile("cp.async.wait_group %0;\n" :: "n"(N) : "memory");
}

// ---------------------------------------------------------------------------
// fp32 -> half elementwise (x)
// ---------------------------------------------------------------------------
__global__ void cvt_h_kernel(const float4* __restrict__ in,
                             uint2* __restrict__ out, int n4)
{
    int i = blockIdx.x * blockDim.x + threadIdx.x;
    if (i < n4) {
        float4 v = in[i];
        __half2 lo = __floats2half2_rn(v.x, v.y);
        __half2 hi = __floats2half2_rn(v.z, v.w);
        uint2 o;
        o.x = *reinterpret_cast<uint32_t*>(&lo);
        o.y = *reinterpret_cast<uint32_t*>(&hi);
        out[i] = o;
    }
}

// ---------------------------------------------------------------------------
// Merged weight transposes: z selects {wq, wk, wv, wo}; in[K,N]f32 -> out[N,K]h
// ---------------------------------------------------------------------------
__global__ void transpose_all_kernel(
    const float* __restrict__ wq, const float* __restrict__ wk,
    const float* __restrict__ wv, const float* __restrict__ wo,
    __half* __restrict__ wqh, __half* __restrict__ wkh,
    __half* __restrict__ wvh, __half* __restrict__ woh)
{
    const int z = blockIdx.z;
    const float* in; __half* out; int N;
    if (z == 0)      { in = wq; out = wqh; N = DIM; }
    else if (z == 1) { in = wk; out = wkh; N = KVDIM; }
    else if (z == 2) { in = wv; out = wvh; N = KVDIM; }
    else             { in = wo; out = woh; N = DIM; }
    int n0 = blockIdx.x * 32;
    if (n0 >= N) return;
    __shared__ float t[32][33];
    int k0 = blockIdx.y * 32;
    int tx = threadIdx.x, ty = threadIdx.y;
#pragma unroll
    for (int i = 0; i < 4; i++)
        t[ty + 8 * i][tx] = in[(size_t)(k0 + ty + 8 * i) * N + n0 + tx];
    __syncthreads();
#pragma unroll
    for (int i = 0; i < 4; i++)
        out[(size_t)(n0 + ty + 8 * i) * DIM + k0 + tx] = __float2half_rn(t[tx][ty + 8 * i]);
}

// ---------------------------------------------------------------------------
// GEMM v4 core (proven 2-CTA/SM config): 128x128 CTA tile, BK=64,
// 256 threads (8 warps 4x2, warp 32x64), 3-stage cp.async, ldmatrix frags.
// ---------------------------------------------------------------------------
#define HSTR 72                       // halfs per smem row (144 B)
#define HSTRB 144
#define HTILE (128 * HSTR)
#define HSTG (2 * HTILE)
#define NSTG 3
#define GEMM_SMEM (NSTG * HSTG * 2)   // 110592 B -> 2 CTAs/SM

struct GemmCore {
    uint32_t sm_u32;
    int tid, lane, warp, g, t4, wm, wn, lm, rr, lrow, lchk;
    uint32_t aoff, boff;
    __device__ __forceinline__ void init(const void* smem) {
        sm_u32 = (uint32_t)__cvta_generic_to_shared(smem);
        tid = threadIdx.x; lane = tid & 31; warp = tid >> 5;
        g = lane >> 2; t4 = lane & 3;
        wm = warp >> 1; wn = warp & 1;
        lm = lane >> 3; rr = lane & 7;
        aoff = (uint32_t)((wm * 32 + (lm & 1) * 8 + rr) * HSTRB + (lm >> 1) * 16);
        boff = (uint32_t)((wn * 64 + (lm >> 1) * 8 + rr) * HSTRB + (lm & 1) * 16);
        lrow = tid >> 3; lchk = tid & 7;
    }
};

__device__ __forceinline__ void gemm_mainloop(
    GemmCore& c, __half* smh, const __half* __restrict__ A,
    const __half* __restrict__ Bt, int bm, int bn, int lda, int ldb,
    int ktiles, float acc[2][8][4])
{
#pragma unroll
    for (int mi = 0; mi < 2; mi++)
#pragma unroll
        for (int ni = 0; ni < 8; ni++)
#pragma unroll
            for (int e = 0; e < 4; e++) acc[mi][ni][e] = 0.f;

    auto issue = [&](int stg, int t) {
        if (t < ktiles) {
            __half* As = smh + stg * HSTG;
            __half* Bs = As + HTILE;
            const int kc = t * 64 + c.lchk * 8;
#pragma unroll
            for (int p = 0; p < 4; p++) {
                int row = c.lrow + p * 32;
                cp_async16(&As[row * HSTR + c.lchk * 8],
                           &A[(size_t)(bm + row) * lda + kc]);
                cp_async16(&Bs[row * HSTR + c.lchk * 8],
                           &Bt[(size_t)(bn + row) * ldb + kc]);
            }
        }
        cp_commit();
    };

    issue(0, 0);
    issue(1, 1);

    for (int t = 0; t < ktiles; t++) {
        cp_wait<1>();
        __syncthreads();
        issue((t + 2) % NSTG, t + 2);

        const uint32_t aBase = c.sm_u32 + (uint32_t)((t % NSTG) * HSTG * 2) + c.aoff;
        const uint32_t bBase = aBase - c.aoff + (uint32_t)(HTILE * 2) + c.boff;

#pragma unroll
        for (int ks = 0; ks < 4; ks++) {
            uint32_t a[2][4], b[4][4];
#pragma unroll
            for (int mi = 0; mi < 2; mi++)
                ldsm_x4(a[mi], aBase + mi * 16 * HSTRB + ks * 32);
#pragma unroll
            for (int p = 0; p < 4; p++)
                ldsm_x4(b[p], bBase + p * 16 * HSTRB + ks * 32);
#pragma unroll
            for (int mi = 0; mi < 2; mi++)
#pragma unroll
                for (int ni = 0; ni < 8; ni++)
                    mma_f16(acc[mi][ni], a[mi], &b[ni >> 1][(ni & 1) * 2], acc[mi][ni]);
        }
    }
}

// ---------------------------------------------------------------------------
// Merged projection GEMM: ONE launch covers wq (1024 tiles), wk (256), wv (256).
// Q/K epilogues fuse RoPE (fp32) and emit half; V emits half [token][d].
// ---------------------------------------------------------------------------
__global__ __launch_bounds__(256, 2) void proj_gemm_kernel(
    const __half* __restrict__ xh,
    const __half* __restrict__ wqh, const __half* __restrict__ wkh,
    const __half* __restrict__ wvh,
    __half* __restrict__ qh, __half* __restrict__ kh, __half* __restrict__ vh,
    const float* __restrict__ fc, const float* __restrict__ fs)
{
    extern __shared__ __half smh[];
    GemmCore c; c.init(smh);

    const int bid = blockIdx.x;
    int mode, bx, by;
    const __half* Bt;
    if (bid < 1024)      { mode = 0; by = bid >> 5; bx = bid & 31; Bt = wqh; }
    else if (bid < 1280) { int t = bid - 1024; mode = 1; by = t >> 3; bx = t & 7; Bt = wkh; }
    else                 { int t = bid - 1280; mode = 2; by = t >> 3; bx = t & 7; Bt = wvh; }

    const int bm = by * 128, bn = bx * 128;
    float acc[2][8][4];
    gemm_mainloop(c, smh, xh, Bt, bm, bn, DIM, DIM, DIM / 64, acc);

    if (mode == 2) {
        // V: half store [token][d] (same single fp32->half rounding as before)
#pragma unroll
        for (int mi = 0; mi < 2; mi++)
#pragma unroll
            for (int ni = 0; ni < 8; ni++) {
                int r0 = bm + c.wm * 32 + mi * 16 + c.g;
                int cc = bn + c.wn * 64 + ni * 8 + c.t4 * 2;
                *reinterpret_cast<__half2*>(&vh[(size_t)r0 * KVDIM + cc]) =
                    __floats2half2_rn(acc[mi][ni][0], acc[mi][ni][1]);
                *reinterpret_cast<__half2*>(&vh[(size_t)(r0 + 8) * KVDIM + cc]) =
                    __floats2half2_rn(acc[mi][ni][2], acc[mi][ni][3]);
            }
    } else {
        // Q/K: fused RoPE on (even, odd) fp32 pair, emit half2
        __half* out = mode ? kh : qh;
        const int ldc = mode ? KVDIM : DIM;
#pragma unroll
        for (int mi = 0; mi < 2; mi++)
#pragma unroll
            for (int ni = 0; ni < 8; ni++) {
                int r0 = bm + c.wm * 32 + mi * 16 + c.g;
                int cc = bn + c.wn * 64 + ni * 8 + c.t4 * 2;
                int fi = (cc & (HD - 1)) >> 1;
                int s0 = r0 & (SEQLEN - 1), s1 = (r0 + 8) & (SEQLEN - 1);
                float c0 = fc[s0 * 64 + fi], n0 = fs[s0 * 64 + fi];
                float c1 = fc[s1 * 64 + fi], n1 = fs[s1 * 64 + fi];
                float e0 = acc[mi][ni][0], o0 = acc[mi][ni][1];
                float e1 = acc[mi][ni][2], o1 = acc[mi][ni][3];
                *reinterpret_cast<__half2*>(&out[(size_t)r0 * ldc + cc]) =
                    __floats2half2_rn(e0 * c0 - o0 * n0, e0 * n0 + o0 * c0);
                *reinterpret_cast<__half2*>(&out[(size_t)(r0 + 8) * ldc + cc]) =
                    __floats2half2_rn(e1 * c1 - o1 * n1, e1 * n1 + o1 * c1);
            }
    }
}

// ---------------------------------------------------------------------------
// Output-projection GEMM (half A/B, fp32 C), v4 tiles
// ---------------------------------------------------------------------------
__global__ __launch_bounds__(256, 2) void gemm_f16_kernel(
    const __half* __restrict__ A, const __half* __restrict__ Bt,
    float* __restrict__ C, int M, int N, int K, int lda, int ldb, int ldc)
{
    extern __shared__ __half smh[];
    GemmCore c; c.init(smh);
    const int bm = blockIdx.y * 128, bn = blockIdx.x * 128;
    float acc[2][8][4];
    gemm_mainloop(c, smh, A, Bt, bm, bn, lda, ldb, K / 64, acc);
#pragma unroll
    for (int mi = 0; mi < 2; mi++)
#pragma unroll
        for (int ni = 0; ni < 8; ni++) {
            int r0 = bm + c.wm * 32 + mi * 16 + c.g;
            int cc = bn + c.wn * 64 + ni * 8 + c.t4 * 2;
            *reinterpret_cast<float2*>(&C[(size_t)r0 * ldc + cc]) =
                make_float2(acc[mi][ni][0], acc[mi][ni][1]);
            *reinterpret_cast<float2*>(&C[(size_t)(r0 + 8) * ldc + cc]) =
                make_float2(acc[mi][ni][2], acc[mi][ni][3]);
        }
}

// ---------------------------------------------------------------------------
// Flash attention v5 (causal, GQA), fp16 operands, fp32 accum/softmax.
// 128 q-rows/CTA, 256 threads, Q in regs, 64-key j-tiles, LPT ordering.
// V loaded in K-layout [key][d]; PV B-fragments via ldmatrix.trans.
// (Measured R14: 278.7 us, tensor 41.9%.)
// ---------------------------------------------------------------------------
#define KSTRH 136                 // K/V/Q-stage smem stride in halfs (272 B)
#define VSTRH 72                  // P smem stride in halfs (144 B)
#define KT_H (64 * KSTRH)         // 8704 halfs (K or V tile)
#define PQ_H (128 * KSTRH)        // 17408 halfs (Q staging; P reuses at VSTRH)
#define ATTN_SMEM ((4 * KT_H + PQ_H) * 2)   // 104448 B

__global__ __launch_bounds__(256) void attn_kernel(
    const __half* __restrict__ Qh, const __half* __restrict__ Kh,
    const __half* __restrict__ Vh, __half* __restrict__ ctxh)
{
    extern __shared__ __half smh[];
    __half* Ksb[2] = { smh, smh + KT_H };
    __half* Vsb[2] = { smh + 2 * KT_H, smh + 3 * KT_H };
    __half* Ps     = smh + 4 * KT_H;
    const uint32_t sm_u32 = (uint32_t)__cvta_generic_to_shared(smh);
    const uint32_t ks_u[2] = { sm_u32, sm_u32 + KT_H * 2 };
    const uint32_t vs_u[2] = { sm_u32 + 2 * KT_H * 2, sm_u32 + 3 * KT_H * 2 };
    const uint32_t ps_u = sm_u32 + 4 * KT_H * 2;

    const int hb = blockIdx.x;
    const int h = hb & (NHEADS - 1), b = hb >> 5;
    const int qt = (gridDim.y - 1) - blockIdx.y;          // LPT
    const int hkv = h >> 2;
    const int tid = threadIdx.x, lane = tid & 31, warp = tid >> 5;
    const int g = lane >> 2, t4 = lane & 3;
    const int lm = lane >> 3, rr = lane & 7;

    const uint32_t qoff = (uint32_t)((warp * 16 + (lm & 1) * 8 + rr) * (KSTRH * 2) + (lm >> 1) * 16);
    const uint32_t poff = (uint32_t)((warp * 16 + (lm & 1) * 8 + rr) * (VSTRH * 2) + (lm >> 1) * 16);
    const uint32_t koff = (uint32_t)(((lm >> 1) * 8 + rr) * (KSTRH * 2) + (lm & 1) * 16);
    // V trans-frag: matrix lm = (d-half = lm>>1, k-half = lm&1)
    const uint32_t voff = (uint32_t)(((lm & 1) * 8 + rr) * (KSTRH * 2) + (lm >> 1) * 16);

    // Stage Q (128 x 128 halfs) into Ps (stride KSTRH), then pull into regs
    {
        const int r0 = tid >> 4, c8 = (tid & 15) * 8;
#pragma unroll
        for (int p = 0; p < 8; p++) {
            int r = r0 + p * 16;
            int gr = b * SEQLEN + qt * 128 + r;
            *reinterpret_cast<uint4*>(&Ps[r * KSTRH + c8]) =
                *reinterpret_cast<const uint4*>(&Qh[(size_t)gr * DIM + h * HD + c8]);
        }
    }
    __syncthreads();
    uint32_t qf[8][4];
#pragma unroll
    for (int ks = 0; ks < 8; ks++)
        ldsm_x4(qf[ks], ps_u + qoff + ks * 32);

    auto issue_kv = [&](int buf, int j) {
        __half* Ks = Ksb[buf];
        __half* Vs = Vsb[buf];
        const int kr0 = tid >> 4, kc8 = (tid & 15) * 8;
#pragma unroll
        for (int p = 0; p < 4; p++) {
            int r = kr0 + p * 16;
            int gr = b * SEQLEN + j * 64 + r;
            cp_async16(&Ks[r * KSTRH + kc8], &Kh[(size_t)gr * KVDIM + hkv * HD + kc8]);
            cp_async16(&Vs[r * KSTRH + kc8], &Vh[(size_t)gr * KVDIM + hkv * HD + kc8]);
        }
        cp_commit();
    };

    float m_s[2] = {-1e30f, -1e30f};
    float l_s[2] = {0.f, 0.f};
    float o[16][4];
#pragma unroll
    for (int di = 0; di < 16; di++)
#pragma unroll
        for (int e = 0; e < 4; e++) o[di][e] = 0.f;

    const float scale = 0.08838834764831845f;
    const int rowbase = qt * 128 + warp * 16;
    const int jmax = 2 * qt + 1;

    issue_kv(0, 0);

    for (int j = 0; j <= jmax; j++) {
        cp_wait<0>();
        __syncthreads();
        if (j + 1 <= jmax) issue_kv((j + 1) & 1, j + 1);

        const bool skip = (j * 64) > rowbase + 15;
        if (!skip) {
            const uint32_t kb = ks_u[j & 1] + koff;
            const uint32_t vb = vs_u[j & 1] + voff;

            float s[8][4];
#pragma unroll
            for (int ni = 0; ni < 8; ni++)
#pragma unroll
                for (int e = 0; e < 4; e++) s[ni][e] = 0.f;

#pragma unroll
            for (int ks = 0; ks < 8; ks++) {
                uint32_t kf[4][4];
#pragma unroll
                for (int p = 0; p < 4; p++)
                    ldsm_x4(kf[p], kb + p * 16 * (KSTRH * 2) + ks * 32);
#pragma unroll
                for (int ni = 0; ni < 8; ni++)
                    mma_f16(s[ni], qf[ks], &kf[ni >> 1][(ni & 1) * 2], s[ni]);
            }

#pragma unroll
            for (int ni = 0; ni < 8; ni++)
#pragma unroll
                for (int e = 0; e < 4; e++) s[ni][e] *= scale;
            if (j * 64 + 63 > rowbase) {
#pragma unroll
                for (int ni = 0; ni < 8; ni++)
#pragma unroll
                    for (int e = 0; e < 4; e++) {
                        int qr = rowbase + g + (e >> 1) * 8;
                        int kc = j * 64 + ni * 8 + t4 * 2 + (e & 1);
                        if (kc > qr) s[ni][e] = -1e30f;
                    }
            }

#pragma unroll
            for (int rw = 0; rw < 2; rw++) {
                float mx = -1e30f;
#pragma unroll
                for (int ni = 0; ni < 8; ni++)
                    mx = fmaxf(mx, fmaxf(s[ni][rw * 2], s[ni][rw * 2 + 1]));
                mx = fmaxf(mx, __shfl_xor_sync(0xffffffffu, mx, 1));
                mx = fmaxf(mx, __shfl_xor_sync(0xffffffffu, mx, 2));
                float nm = fmaxf(m_s[rw], mx);
                float alpha = __expf(m_s[rw] - nm);
                m_s[rw] = nm;
                float rsum = 0.f;
#pragma unroll
                for (int ni = 0; ni < 8; ni++) {
#pragma unroll
                    for (int cc = 0; cc < 2; cc++) {
                        float pv = __expf(s[ni][rw * 2 + cc] - nm);
                        s[ni][rw * 2 + cc] = pv;
                        rsum += pv;
                    }
                }
                rsum += __shfl_xor_sync(0xffffffffu, rsum, 1);
                rsum += __shfl_xor_sync(0xffffffffu, rsum, 2);
                l_s[rw] = l_s[rw] * alpha + rsum;
#pragma unroll
                for (int di = 0; di < 16; di++) {
                    o[di][rw * 2] *= alpha;
                    o[di][rw * 2 + 1] *= alpha;
                }
            }

            __syncwarp();
#pragma unroll
            for (int ni = 0; ni < 8; ni++)
#pragma unroll
                for (int rw = 0; rw < 2; rw++) {
                    int pr = warp * 16 + g + rw * 8;
                    int pc = ni * 8 + t4 * 2;
                    *reinterpret_cast<__half2*>(&Ps[pr * VSTRH + pc]) =
                        __floats2half2_rn(s[ni][rw * 2], s[ni][rw * 2 + 1]);
                }
            __syncwarp();

            // O += P @ V : V B-frags via trans-ldsm on [key][d] tile
#pragma unroll
            for (int ks = 0; ks < 4; ks++) {
                uint32_t a[4], vf[8][4];
                ldsm_x4(a, ps_u + poff + ks * 32);
#pragma unroll
                for (int p = 0; p < 8; p++)
                    ldsm_x4_trans(vf[p], vb + ks * 16 * (KSTRH * 2) + p * 32);
#pragma unroll
                for (int di = 0; di < 16; di++)
                    mma_f16(o[di], a, &vf[di >> 1][(di & 1) * 2], o[di]);
            }
        }
    }

#pragma unroll
    for (int rw = 0; rw < 2; rw++) {
        float inv = 1.0f / l_s[rw];
        int gr = b * SEQLEN + rowbase + g + rw * 8;
#pragma unroll
        for (int di = 0; di < 16; di++) {
            *reinterpret_cast<__half2*>(
                &ctxh[(size_t)gr * DIM + h * HD + di * 8 + t4 * 2]) =
                __floats2half2_rn(o[di][rw * 2] * inv, o[di][rw * 2 + 1] * inv);
        }
    }
}

// ---------------------------------------------------------------------------
// launch
// ---------------------------------------------------------------------------
extern "C" void kernel_launch(void* const* d_in, const int* in_sizes, int n_in,
                              void* d_out, int out_size)
{
    const float* x  = (const float*)d_in[0];
    const float* wq = (const float*)d_in[1];
    const float* wk = (const float*)d_in[2];
    const float* wv = (const float*)d_in[3];
    const float* wo = (const float*)d_in[4];
    const float* fc = (const float*)d_in[5];
    const float* fs = (const float*)d_in[6];
    // d_in[7] = mask (causal, applied analytically), d_in[8] = start_pos (0)
    float* out = (float*)d_out;

    __half *qh, *kh, *vh, *ctxh, *xh, *wqh, *wkh, *wvh, *woh;
    cudaGetSymbolAddress((void**)&qh,   g_qh);
    cudaGetSymbolAddress((void**)&kh,   g_kh);
    cudaGetSymbolAddress((void**)&vh,   g_vh);
    cudaGetSymbolAddress((void**)&ctxh, g_ctxh);
    cudaGetSymbolAddress((void**)&xh,   g_xh);
    cudaGetSymbolAddress((void**)&wqh,  g_wqh);
    cudaGetSymbolAddress((void**)&wkh,  g_wkh);
    cudaGetSymbolAddress((void**)&wvh,  g_wvh);
    cudaGetSymbolAddress((void**)&woh,  g_woh);

    cudaFuncSetAttribute(proj_gemm_kernel,
                         cudaFuncAttributeMaxDynamicSharedMemorySize, GEMM_SMEM);
    cudaFuncSetAttribute(gemm_f16_kernel,
                         cudaFuncAttributeMaxDynamicSharedMemorySize, GEMM_SMEM);
    cudaFuncSetAttribute(attn_kernel,
                         cudaFuncAttributeMaxDynamicSharedMemorySize, ATTN_SMEM);

    // x -> half; all 4 weight transposes in ONE launch
    int n4_big = MROWS * DIM / 4;
    cvt_h_kernel<<<(n4_big + 255) / 256, 256>>>((const float4*)x, (uint2*)xh, n4_big);
    transpose_all_kernel<<<dim3(DIM / 32, DIM / 32, 4), dim3(32, 8)>>>(
        wq, wk, wv, wo, wqh, wkh, wvh, woh);

    // ALL projections in ONE 1536-CTA launch; RoPE fused into Q/K epilogues;
    // V emitted as half [token][d] directly
    proj_gemm_kernel<<<1536, 256, GEMM_SMEM>>>(xh, wqh, wkh, wvh, qh, kh, vh, fc, fs);

    // Causal flash attention (half in/out), trans-ldsm V path, LPT-ordered
    attn_kernel<<<dim3(NHEADS * BSZ, SEQLEN / 128), 256, ATTN_SMEM>>>(qh, kh, vh, ctxh);

    // Output projection (half ctx @ half wo -> fp32 out)
    gemm_f16_kernel<<<dim3(DIM / 128, MROWS / 128), 256, GEMM_SMEM>>>(
        ctxh, woh, out, MROWS, DIM, DIM, DIM, DIM, DIM);
}